// round 1
// baseline (speedup 1.0000x reference)
#include <cuda_runtime.h>
#include <math.h>

#define BB    8
#define CIN   64
#define COUT  64
#define NPTS  32768
#define RR    32
#define R3    32768

// ---------------- scratch (static __device__ — no allocations) ----------------
__device__ float g_featT[(size_t)BB*NPTS*CIN];   // [b][n][c]
__device__ float g_acc  [(size_t)BB*R3*CIN];     // [b][x][y][z][c]  (scatter target)
__device__ float g_cnt  [BB*R3];
__device__ float g_vox  [(size_t)BB*R3*CIN];     // [b][x][y][c][z]  (conv1 input)
__device__ float g_vox1 [(size_t)BB*R3*COUT];    // [b][x][y][c][z]  (conv1 out / conv2 in)
__device__ float g_vox2 [(size_t)BB*R3*COUT];    // [b][x][y][z][c]  (conv2 out, gather-friendly)
__device__ float g_wt   [2*27*64*64];            // [which][tap][ci][co]
__device__ float g_mean [BB*3];
__device__ float g_scale[BB];

// ---------------- f32x2 helpers ----------------
__device__ __forceinline__ unsigned long long pk2(float lo, float hi){
    unsigned long long r;
    asm("mov.b64 %0, {%1, %2};" : "=l"(r) : "f"(lo), "f"(hi));
    return r;
}
__device__ __forceinline__ void fma2(unsigned long long &d, unsigned long long a, unsigned long long b){
    asm("fma.rn.f32x2 %0, %1, %2, %0;" : "+l"(d) : "l"(a), "l"(b));
}
__device__ __forceinline__ void upk2(float &lo, float &hi, unsigned long long v){
    asm("mov.b64 {%0, %1}, %2;" : "=f"(lo), "=f"(hi) : "l"(v));
}

// ---------------- zero scratch ----------------
__global__ void k_zero(){
    size_t stride = (size_t)gridDim.x * blockDim.x;
    size_t t0 = (size_t)blockIdx.x * blockDim.x + threadIdx.x;
    size_t totA = (size_t)BB*R3*CIN;
    for(size_t i = t0; i < totA; i += stride) g_acc[i] = 0.f;
    for(size_t i = t0; i < (size_t)BB*R3; i += stride) g_cnt[i] = 0.f;
}

// ---------------- per-batch mean ----------------
__global__ void k_mean(const float* __restrict__ coords){
    __shared__ float sh[256];
    int b = blockIdx.x, tid = threadIdx.x;
    for(int a = 0; a < 3; a++){
        float s = 0.f;
        for(int n = tid; n < NPTS; n += 256) s += coords[((size_t)b*3 + a)*NPTS + n];
        sh[tid] = s; __syncthreads();
        for(int off = 128; off; off >>= 1){ if(tid < off) sh[tid] += sh[tid+off]; __syncthreads(); }
        if(tid == 0) g_mean[b*3 + a] = sh[0] / (float)NPTS;
        __syncthreads();
    }
}

// ---------------- per-batch max radius -> scale ----------------
__global__ void k_radius(const float* __restrict__ coords){
    __shared__ float sh[256];
    int b = blockIdx.x, tid = threadIdx.x;
    float m0 = g_mean[b*3+0], m1 = g_mean[b*3+1], m2 = g_mean[b*3+2];
    float mx = 0.f;
    for(int n = tid; n < NPTS; n += 256){
        float dx = coords[((size_t)b*3+0)*NPTS + n] - m0;
        float dy = coords[((size_t)b*3+1)*NPTS + n] - m1;
        float dz = coords[((size_t)b*3+2)*NPTS + n] - m2;
        float d2 = dx*dx + dy*dy + dz*dz;
        mx = fmaxf(mx, d2);
    }
    sh[tid] = mx; __syncthreads();
    for(int off = 128; off; off >>= 1){ if(tid < off) sh[tid] = fmaxf(sh[tid], sh[tid+off]); __syncthreads(); }
    if(tid == 0) g_scale[b] = 1.0f / (2.0f * sqrtf(sh[0]) * (1.0f + 1e-6f));
}

// ---------------- transpose features [b][c][n] -> [b][n][c] ----------------
__global__ void k_tfeat(const float* __restrict__ f){
    __shared__ float s[32][33];
    int b = blockIdx.z;
    int n = blockIdx.x*32 + threadIdx.x;
    int cbase = blockIdx.y*32;
    #pragma unroll
    for(int j = 0; j < 4; j++){
        int c = cbase + threadIdx.y + j*8;
        s[threadIdx.y + j*8][threadIdx.x] = f[((size_t)b*CIN + c)*NPTS + n];
    }
    __syncthreads();
    int c2 = cbase + threadIdx.x;
    #pragma unroll
    for(int j = 0; j < 4; j++){
        int n2 = blockIdx.x*32 + threadIdx.y + j*8;
        g_featT[((size_t)b*NPTS + n2)*CIN + c2] = s[threadIdx.x][threadIdx.y + j*8];
    }
}

// ---------------- weight transform: w[co][ci][27] -> wt[tap][ci][co] ----------------
__global__ void k_prepw(const float* __restrict__ w1, const float* __restrict__ w2){
    int idx = blockIdx.x*256 + threadIdx.x;
    if(idx >= 2*110592) return;
    int which = idx / 110592;
    int i = idx - which*110592;
    int co  = i & 63;
    int ci  = (i >> 6) & 63;
    int tap = i >> 12;
    const float* src = which ? w2 : w1;
    g_wt[idx] = src[(co*64 + ci)*27 + tap];
}

// ---------------- trilinear scatter (atomics) ----------------
__global__ void k_scatter(const float* __restrict__ coords){
    int t = blockIdx.x*256 + threadIdx.x;
    int c = t & 63;
    int p = t >> 6;                  // global point id
    int b = p >> 15;
    int n = p & (NPTS-1);
    float sc = g_scale[b];
    float vx = fminf(fmaxf(((coords[((size_t)b*3+0)*NPTS+n] - g_mean[b*3+0])*sc + 0.5f)*32.f, 0.f), 31.f);
    float vy = fminf(fmaxf(((coords[((size_t)b*3+1)*NPTS+n] - g_mean[b*3+1])*sc + 0.5f)*32.f, 0.f), 31.f);
    float vz = fminf(fmaxf(((coords[((size_t)b*3+2)*NPTS+n] - g_mean[b*3+2])*sc + 0.5f)*32.f, 0.f), 31.f);
    int lx = (int)floorf(vx), ly = (int)floorf(vy), lz = (int)floorf(vz);
    float fx = vx - lx, fy = vy - ly, fz = vz - lz;
    float f = g_featT[(size_t)p*64 + c];
    #pragma unroll
    for(int corner = 0; corner < 8; corner++){
        int dxb = corner >> 2, dyb = (corner >> 1) & 1, dzb = corner & 1;
        int xi = min(lx + dxb, 31), yi = min(ly + dyb, 31), zi = min(lz + dzb, 31);
        float w = (dxb ? fx : 1.f-fx) * (dyb ? fy : 1.f-fy) * (dzb ? fz : 1.f-fz);
        int vi = (xi*32 + yi)*32 + zi;
        atomicAdd(&g_acc[((size_t)b*R3 + vi)*64 + c], w * f);
        if(c == 0) atomicAdd(&g_cnt[b*R3 + vi], w);
    }
}

// ---------------- normalize + transpose to conv layout [b][x][y][c][z] ----------------
__global__ void k_norm(){
    __shared__ float s[2080];
    int blk = blockIdx.x;            // 8192 = B*32*32
    int b = blk >> 10, xy = blk & 1023;
    int tid = threadIdx.x;
    size_t base = ((size_t)b*R3 + (size_t)xy*32)*64;
    int cbase = b*R3 + xy*32;
    for(int i = tid; i < 2048; i += 256){
        int z = i >> 6, c = i & 63;
        float cw = g_cnt[cbase + z];
        s[z*65 + c] = g_acc[base + i] / fmaxf(cw, 1e-8f);
    }
    __syncthreads();
    size_t obase = ((size_t)b*1024 + xy)*2048;
    for(int i = tid; i < 2048; i += 256){
        int c = i >> 5, z = i & 31;
        g_vox[obase + (size_t)c*32 + z] = s[z*65 + c];
    }
}

// ---------------- 3x3x3 conv + BN + leaky, 64->64, tile 4x4x16 ----------------
#define XYSTR 1155
#define SMEM_CONV_BYTES ((36*XYSTR + 4096)*4)

__global__ void __launch_bounds__(256, 1) k_conv(int mode,
        const float* __restrict__ cb, const float* __restrict__ bg,
        const float* __restrict__ bb, const float* __restrict__ bm,
        const float* __restrict__ bv){
    extern __shared__ float smem[];
    float* s_in = smem;                      // [xy(36)][ci(64)][hz(18)], xy stride 1155
    float* s_w  = smem + 36*XYSTR;           // [ci(64)][co(64)] per tap
    const float* __restrict__ in  = mode ? g_vox1 : g_vox;
    float*       __restrict__ out = mode ? g_vox2 : g_vox1;
    const float* __restrict__ wt  = g_wt + mode*110592;

    int tid = threadIdx.x;
    int cta = blockIdx.x;
    int b = cta >> 7; int rem = cta & 127;
    int tz = rem & 1; int ty = (rem >> 1) & 7; int tx = rem >> 4;
    int x0 = tx*4, y0 = ty*4, z0 = tz*16;

    // load halo input tile: global [b][x][y][ci][z] -> smem [xy][ci][hz]
    for(int i = tid; i < 36*64*18; i += 256){
        int hz = i % 18; int r2 = i / 18; int ci = r2 & 63; int xy = r2 >> 6;
        int gx = x0 - 1 + xy/6;
        int gy = y0 - 1 + (xy - (xy/6)*6);
        int gz = z0 - 1 + hz;
        float v = 0.f;
        if((unsigned)gx < 32u && (unsigned)gy < 32u && (unsigned)gz < 32u)
            v = in[((((size_t)b*32 + gx)*32 + gy)*64 + ci)*32 + gz];
        s_in[xy*XYSTR + ci*18 + hz] = v;
    }

    int lane = tid & 31, cog = tid >> 5;
    int lx = (lane & 15) >> 2, ly = lane & 3, zh = lane >> 4;
    int cog2 = cog*2;

    unsigned long long acc[8][4];
    #pragma unroll
    for(int a = 0; a < 8; a++)
        #pragma unroll
        for(int k = 0; k < 4; k++) acc[a][k] = 0ull;

    for(int tap = 0; tap < 27; tap++){
        __syncthreads();
        { // load 64x64 weight slice for this tap
            const float4* wsrc = (const float4*)(wt + tap*4096);
            float4* wdst = (float4*)s_w;
            for(int i = tid; i < 1024; i += 256) wdst[i] = wsrc[i];
        }
        __syncthreads();
        int dx = tap/9, dy = (tap/3)%3, dz = tap%3;
        const float* pin = s_in + ((lx+dx)*6 + (ly+dy))*XYSTR + zh*8 + dz;
        const float4* pw4 = (const float4*)s_w;
        #pragma unroll 4
        for(int ci = 0; ci < 64; ci++){
            float4 wA = pw4[ci*16 + cog2];
            float4 wB = pw4[ci*16 + cog2 + 1];
            const float* q = pin + ci*18;
            float i0=q[0], i1=q[1], i2=q[2], i3=q[3], i4=q[4], i5=q[5], i6=q[6], i7=q[7];
            unsigned long long p0 = pk2(i0,i1), p1 = pk2(i2,i3), p2 = pk2(i4,i5), p3 = pk2(i6,i7);
            unsigned long long w;
            w = pk2(wA.x,wA.x); fma2(acc[0][0],w,p0); fma2(acc[0][1],w,p1); fma2(acc[0][2],w,p2); fma2(acc[0][3],w,p3);
            w = pk2(wA.y,wA.y); fma2(acc[1][0],w,p0); fma2(acc[1][1],w,p1); fma2(acc[1][2],w,p2); fma2(acc[1][3],w,p3);
            w = pk2(wA.z,wA.z); fma2(acc[2][0],w,p0); fma2(acc[2][1],w,p1); fma2(acc[2][2],w,p2); fma2(acc[2][3],w,p3);
            w = pk2(wA.w,wA.w); fma2(acc[3][0],w,p0); fma2(acc[3][1],w,p1); fma2(acc[3][2],w,p2); fma2(acc[3][3],w,p3);
            w = pk2(wB.x,wB.x); fma2(acc[4][0],w,p0); fma2(acc[4][1],w,p1); fma2(acc[4][2],w,p2); fma2(acc[4][3],w,p3);
            w = pk2(wB.y,wB.y); fma2(acc[5][0],w,p0); fma2(acc[5][1],w,p1); fma2(acc[5][2],w,p2); fma2(acc[5][3],w,p3);
            w = pk2(wB.z,wB.z); fma2(acc[6][0],w,p0); fma2(acc[6][1],w,p1); fma2(acc[6][2],w,p2); fma2(acc[6][3],w,p3);
            w = pk2(wB.w,wB.w); fma2(acc[7][0],w,p0); fma2(acc[7][1],w,p1); fma2(acc[7][2],w,p2); fma2(acc[7][3],w,p3);
        }
    }

    // epilogue: fold conv bias + BN, leaky relu, store
    int x = x0 + lx, y = y0 + ly;
    #pragma unroll
    for(int a = 0; a < 8; a++){
        int co = cog*8 + a;
        float s  = bg[co] * rsqrtf(bv[co] + 1e-4f);
        float bc = (cb[co] - bm[co]) * s + bb[co];
        float vals[8];
        #pragma unroll
        for(int kp = 0; kp < 4; kp++) upk2(vals[2*kp], vals[2*kp+1], acc[a][kp]);
        #pragma unroll
        for(int k = 0; k < 8; k++){
            float yv = vals[k]*s + bc;
            yv = (yv > 0.f) ? yv : 0.1f*yv;
            int z = z0 + zh*8 + k;
            if(mode)  // layout B: [b][x][y][z][c]
                out[((((size_t)b*32 + x)*32 + y)*32 + z)*64 + co] = yv;
            else      // layout A: [b][x][y][c][z]
                out[((((size_t)b*32 + x)*32 + y)*64 + co)*32 + z] = yv;
        }
    }
}

// ---------------- devoxelize (gather) + point-branch MLP, write fused ----------------
__global__ void __launch_bounds__(256) k_devox(const float* __restrict__ coords,
        const float* __restrict__ mlpw, const float* __restrict__ mlpb,
        const float* __restrict__ bg, const float* __restrict__ bb,
        const float* __restrict__ bm, const float* __restrict__ bv,
        float* __restrict__ outp){
    __shared__ float s_feat[32*65];
    __shared__ float s_mw[64*65];
    __shared__ int   s_ci[256];
    __shared__ float s_cw[256];
    int tid = threadIdx.x;
    int blk = blockIdx.x;            // 8192 = B * (N/32)
    int b = blk >> 10; int n0 = (blk & 1023)*32;

    const float* fsrc = g_featT + ((size_t)b*NPTS + n0)*64;
    for(int i = tid; i < 2048; i += 256) s_feat[(i>>6)*65 + (i&63)] = fsrc[i];
    for(int i = tid; i < 4096; i += 256){ int co = i>>6, ci = i&63; s_mw[ci*65 + co] = mlpw[i]; }
    {
        int pn = tid >> 3, corner = tid & 7;
        int n = n0 + pn;
        float sc = g_scale[b];
        float vx = fminf(fmaxf(((coords[((size_t)b*3+0)*NPTS+n] - g_mean[b*3+0])*sc + 0.5f)*32.f, 0.f), 31.f);
        float vy = fminf(fmaxf(((coords[((size_t)b*3+1)*NPTS+n] - g_mean[b*3+1])*sc + 0.5f)*32.f, 0.f), 31.f);
        float vz = fminf(fmaxf(((coords[((size_t)b*3+2)*NPTS+n] - g_mean[b*3+2])*sc + 0.5f)*32.f, 0.f), 31.f);
        int lx = (int)floorf(vx), ly = (int)floorf(vy), lz = (int)floorf(vz);
        float fx = vx - lx, fy = vy - ly, fz = vz - lz;
        int dxb = corner >> 2, dyb = (corner >> 1) & 1, dzb = corner & 1;
        int xi = min(lx+dxb,31), yi = min(ly+dyb,31), zi = min(lz+dzb,31);
        s_ci[tid] = (xi*32 + yi)*32 + zi;
        s_cw[tid] = (dxb ? fx : 1.f-fx) * (dyb ? fy : 1.f-fy) * (dzb ? fz : 1.f-fz);
    }
    __syncthreads();

    int pn = tid & 31, cg = tid >> 5;
    int n = n0 + pn;
    float m[8];
    #pragma unroll
    for(int j = 0; j < 8; j++) m[j] = 0.f;
    for(int ci = 0; ci < 64; ci++){
        float f = s_feat[pn*65 + ci];
        #pragma unroll
        for(int j = 0; j < 8; j++) m[j] += s_mw[ci*65 + cg*8 + j] * f;
    }
    float res[8];
    #pragma unroll
    for(int j = 0; j < 8; j++){
        int co = cg*8 + j;
        float s  = bg[co] * rsqrtf(bv[co] + 1e-4f);
        float bc = (mlpb[co] - bm[co]) * s + bb[co];
        res[j] = fmaxf(m[j]*s + bc, 0.f);
    }
    #pragma unroll
    for(int corner = 0; corner < 8; corner++){
        int vi = s_ci[pn*8 + corner];
        float w = s_cw[pn*8 + corner];
        const float4* src = (const float4*)(g_vox2 + ((size_t)b*R3 + vi)*64 + cg*8);
        float4 v0 = src[0], v1 = src[1];
        res[0] += w*v0.x; res[1] += w*v0.y; res[2] += w*v0.z; res[3] += w*v0.w;
        res[4] += w*v1.x; res[5] += w*v1.y; res[6] += w*v1.z; res[7] += w*v1.w;
    }
    #pragma unroll
    for(int j = 0; j < 8; j++)
        outp[((size_t)b*64 + cg*8 + j)*NPTS + n] = res[j];
}

// ---------------- copy coords to output tail ----------------
__global__ void k_copy(const float* __restrict__ coords, float* __restrict__ dst){
    int i = blockIdx.x*256 + threadIdx.x;
    if(i < BB*3*NPTS) dst[i] = coords[i];
}

// ---------------- launch ----------------
extern "C" void kernel_launch(void* const* d_in, const int* in_sizes, int n_in,
                              void* d_out, int out_size){
    const float* features = (const float*)d_in[0];
    const float* coords   = (const float*)d_in[1];
    const float* c1w = (const float*)d_in[2];
    const float* c1b = (const float*)d_in[3];
    const float* b1g = (const float*)d_in[4];
    const float* b1b = (const float*)d_in[5];
    const float* b1m = (const float*)d_in[6];
    const float* b1v = (const float*)d_in[7];
    const float* c2w = (const float*)d_in[8];
    const float* c2b = (const float*)d_in[9];
    const float* b2g = (const float*)d_in[10];
    const float* b2b = (const float*)d_in[11];
    const float* b2m = (const float*)d_in[12];
    const float* b2v = (const float*)d_in[13];
    const float* mw  = (const float*)d_in[14];
    const float* mb  = (const float*)d_in[15];
    const float* bpg = (const float*)d_in[16];
    const float* bpb = (const float*)d_in[17];
    const float* bpm = (const float*)d_in[18];
    const float* bpv = (const float*)d_in[19];
    float* out = (float*)d_out;

    cudaFuncSetAttribute(k_conv, cudaFuncAttributeMaxDynamicSharedMemorySize, SMEM_CONV_BYTES);

    k_zero   <<<1024, 256>>>();
    k_mean   <<<BB,   256>>>(coords);
    k_radius <<<BB,   256>>>(coords);
    k_tfeat  <<<dim3(NPTS/32, CIN/32, BB), dim3(32, 8)>>>(features);
    k_prepw  <<<(2*110592 + 255)/256, 256>>>(c1w, c2w);
    k_scatter<<<(BB*NPTS*64)/256, 256>>>(coords);
    k_norm   <<<BB*1024, 256>>>();
    k_conv   <<<1024, 256, SMEM_CONV_BYTES>>>(0, c1b, b1g, b1b, b1m, b1v);
    k_conv   <<<1024, 256, SMEM_CONV_BYTES>>>(1, c2b, b2g, b2b, b2m, b2v);
    k_devox  <<<BB*(NPTS/32), 256>>>(coords, mw, mb, bpg, bpb, bpm, bpv, out);
    k_copy   <<<(BB*3*NPTS + 255)/256, 256>>>(coords, out + (size_t)BB*COUT*NPTS);
}

// round 3
// speedup vs baseline: 1.9434x; 1.9434x over previous
#include <cuda_runtime.h>
#include <cuda_bf16.h>
#include <math.h>
#include <stdint.h>

#define BB    8
#define CIN   64
#define COUT  64
#define NPTS  32768
#define R3    32768

// ---------------- scratch (static __device__ — no allocations) ----------------
__device__ float g_featT[(size_t)BB*NPTS*CIN];            // [b][n][c]
__device__ float g_acc  [(size_t)BB*R3*CIN];              // [b][x][y][z][c]
__device__ float g_cnt  [BB*R3];
__device__ __nv_bfloat16 g_v0h[(size_t)BB*R3*CIN];        // voxelized hi  [b][x][y][z][c]
__device__ __nv_bfloat16 g_v0l[(size_t)BB*R3*CIN];        // voxelized lo
__device__ __nv_bfloat16 g_v1h[(size_t)BB*R3*COUT];       // conv1 out hi
__device__ __nv_bfloat16 g_v1l[(size_t)BB*R3*COUT];       // conv1 out lo
__device__ float g_vox2[(size_t)BB*R3*COUT];              // conv2 out fp32 [b][x][y][z][c]
__device__ __nv_bfloat16 g_wall[108*64*64];               // [which*54 + hl*27 + tap][co][ci]
__device__ float g_mean [BB*3];
__device__ float g_scale[BB];

// ---------------- helpers ----------------
__device__ __forceinline__ uint32_t smem_u32(const void* p){
    uint32_t a;
    asm("{ .reg .u64 t; cvta.to.shared.u64 t, %1; cvt.u32.u64 %0, t; }" : "=r"(a) : "l"(p));
    return a;
}
__device__ __forceinline__ void ldmx4(uint32_t &r0, uint32_t &r1, uint32_t &r2, uint32_t &r3, uint32_t a){
    asm volatile("ldmatrix.sync.aligned.m8n8.x4.shared.b16 {%0,%1,%2,%3}, [%4];"
        : "=r"(r0), "=r"(r1), "=r"(r2), "=r"(r3) : "r"(a));
}
__device__ __forceinline__ void mma16816(float* c, const uint32_t* a, const uint32_t* b){
    asm volatile("mma.sync.aligned.m16n8k16.row.col.f32.bf16.bf16.f32 "
        "{%0,%1,%2,%3}, {%4,%5,%6,%7}, {%8,%9}, {%0,%1,%2,%3};"
        : "+f"(c[0]), "+f"(c[1]), "+f"(c[2]), "+f"(c[3])
        : "r"(a[0]), "r"(a[1]), "r"(a[2]), "r"(a[3]), "r"(b[0]), "r"(b[1]));
}

// ---------------- zero scratch ----------------
__global__ void k_zero(){
    size_t stride = (size_t)gridDim.x * blockDim.x;
    size_t t0 = (size_t)blockIdx.x * blockDim.x + threadIdx.x;
    for(size_t i = t0; i < (size_t)BB*R3*CIN; i += stride) g_acc[i] = 0.f;
    for(size_t i = t0; i < (size_t)BB*R3; i += stride) g_cnt[i] = 0.f;
}

// ---------------- per-batch mean ----------------
__global__ void k_mean(const float* __restrict__ coords){
    __shared__ float sh[256];
    int b = blockIdx.x, tid = threadIdx.x;
    for(int a = 0; a < 3; a++){
        float s = 0.f;
        for(int n = tid; n < NPTS; n += 256) s += coords[((size_t)b*3 + a)*NPTS + n];
        sh[tid] = s; __syncthreads();
        for(int off = 128; off; off >>= 1){ if(tid < off) sh[tid] += sh[tid+off]; __syncthreads(); }
        if(tid == 0) g_mean[b*3 + a] = sh[0] / (float)NPTS;
        __syncthreads();
    }
}

// ---------------- per-batch max radius -> scale ----------------
__global__ void k_radius(const float* __restrict__ coords){
    __shared__ float sh[256];
    int b = blockIdx.x, tid = threadIdx.x;
    float m0 = g_mean[b*3+0], m1 = g_mean[b*3+1], m2 = g_mean[b*3+2];
    float mx = 0.f;
    for(int n = tid; n < NPTS; n += 256){
        float dx = coords[((size_t)b*3+0)*NPTS + n] - m0;
        float dy = coords[((size_t)b*3+1)*NPTS + n] - m1;
        float dz = coords[((size_t)b*3+2)*NPTS + n] - m2;
        mx = fmaxf(mx, dx*dx + dy*dy + dz*dz);
    }
    sh[tid] = mx; __syncthreads();
    for(int off = 128; off; off >>= 1){ if(tid < off) sh[tid] = fmaxf(sh[tid], sh[tid+off]); __syncthreads(); }
    if(tid == 0) g_scale[b] = 1.0f / (2.0f * sqrtf(sh[0]) * (1.0f + 1e-6f));
}

// ---------------- transpose features [b][c][n] -> [b][n][c] ----------------
__global__ void k_tfeat(const float* __restrict__ f){
    __shared__ float s[32][33];
    int b = blockIdx.z;
    int n = blockIdx.x*32 + threadIdx.x;
    int cbase = blockIdx.y*32;
    #pragma unroll
    for(int j = 0; j < 4; j++){
        int c = cbase + threadIdx.y + j*8;
        s[threadIdx.y + j*8][threadIdx.x] = f[((size_t)b*CIN + c)*NPTS + n];
    }
    __syncthreads();
    int c2 = cbase + threadIdx.x;
    #pragma unroll
    for(int j = 0; j < 4; j++){
        int n2 = blockIdx.x*32 + threadIdx.y + j*8;
        g_featT[((size_t)b*NPTS + n2)*CIN + c2] = s[threadIdx.x][threadIdx.y + j*8];
    }
}

// ---------------- weight prep: w[co][ci][tap] -> bf16 hi/lo [plane][co][ci] ----------------
__global__ void k_prepw(const float* __restrict__ w1, const float* __restrict__ w2){
    int idx = blockIdx.x*256 + threadIdx.x;   // 2*27*4096 = 221184
    if(idx >= 221184) return;
    int which = idx / 110592;
    int r = idx - which*110592;
    int tap = r >> 12;
    int co  = (r >> 6) & 63;
    int ci  = r & 63;
    const float* src = which ? w2 : w1;
    float v = src[(co*64 + ci)*27 + tap];
    __nv_bfloat16 h = __float2bfloat16(v);
    float lo = v - __bfloat162float(h);
    g_wall[(which*54 + tap)*4096 + co*64 + ci]      = h;
    g_wall[(which*54 + 27 + tap)*4096 + co*64 + ci] = __float2bfloat16(lo);
}

// ---------------- trilinear scatter (atomics) ----------------
__global__ void k_scatter(const float* __restrict__ coords){
    int t = blockIdx.x*256 + threadIdx.x;
    int c = t & 63;
    int p = t >> 6;
    int b = p >> 15;
    int n = p & (NPTS-1);
    float sc = g_scale[b];
    float vx = fminf(fmaxf(((coords[((size_t)b*3+0)*NPTS+n] - g_mean[b*3+0])*sc + 0.5f)*32.f, 0.f), 31.f);
    float vy = fminf(fmaxf(((coords[((size_t)b*3+1)*NPTS+n] - g_mean[b*3+1])*sc + 0.5f)*32.f, 0.f), 31.f);
    float vz = fminf(fmaxf(((coords[((size_t)b*3+2)*NPTS+n] - g_mean[b*3+2])*sc + 0.5f)*32.f, 0.f), 31.f);
    int lx = (int)floorf(vx), ly = (int)floorf(vy), lz = (int)floorf(vz);
    float fx = vx - lx, fy = vy - ly, fz = vz - lz;
    float f = g_featT[(size_t)p*64 + c];
    #pragma unroll
    for(int corner = 0; corner < 8; corner++){
        int dxb = corner >> 2, dyb = (corner >> 1) & 1, dzb = corner & 1;
        int xi = min(lx + dxb, 31), yi = min(ly + dyb, 31), zi = min(lz + dzb, 31);
        float w = (dxb ? fx : 1.f-fx) * (dyb ? fy : 1.f-fy) * (dzb ? fz : 1.f-fz);
        int vi = (xi*32 + yi)*32 + zi;
        atomicAdd(&g_acc[((size_t)b*R3 + vi)*64 + c], w * f);
        if(c == 0) atomicAdd(&g_cnt[b*R3 + vi], w);
    }
}

// ---------------- normalize + hi/lo bf16 split ----------------
__global__ void k_hilo(){
    size_t i = (size_t)blockIdx.x*256 + threadIdx.x;   // 16.7M
    float cw = g_cnt[i >> 6];
    float v = g_acc[i] / fmaxf(cw, 1e-8f);
    __nv_bfloat16 h = __float2bfloat16(v);
    g_v0h[i] = h;
    g_v0l[i] = __float2bfloat16(v - __bfloat162float(h));
}

// ---------------- HMMA conv: 3x3x3, 64->64, bf16 hi/lo 3-pass, BN + leaky ----------------
// smem layout (bytes): A_hi @0 (51840), A_lo @51840 (51840), W_hi @103680 (9216), W_lo @112896 (9216)
#define SM_AL 51840
#define SM_WH 103680
#define SM_WL 112896
#define CONV_SMEM 122112

__global__ void __launch_bounds__(256, 1) k_conv_mma(int mode,
        const float* __restrict__ cb, const float* __restrict__ bg,
        const float* __restrict__ bb, const float* __restrict__ bm,
        const float* __restrict__ bv){
    extern __shared__ char sm[];
    __shared__ float s_scale[64], s_bias[64];

    const __nv_bfloat16* __restrict__ Ah = mode ? g_v1h : g_v0h;
    const __nv_bfloat16* __restrict__ Al = mode ? g_v1l : g_v0l;
    const __nv_bfloat16* __restrict__ Wg = g_wall + (size_t)mode*54*4096;

    int tid = threadIdx.x;
    int cta = blockIdx.x;
    int b  = cta >> 8;
    int x0 = ((cta >> 5) & 7) * 4;
    int y0 = ((cta >> 2) & 7) * 4;
    int z0 = (cta & 3) * 8;

    if(tid < 64){
        float s = bg[tid] * rsqrtf(bv[tid] + 1e-4f);
        s_scale[tid] = s;
        s_bias[tid]  = (cb[tid] - bm[tid]) * s + bb[tid];
    }

    // ---- load halo 6x6x10 x 64ci (hi+lo), row pitch 144B ----
    for(int i = tid; i < 2880; i += 256){
        int hv = i >> 3, cg = i & 7;
        int hx = hv/60; int rem = hv - hx*60; int hy = rem/10; int hz = rem - hy*10;
        int gx = x0 - 1 + hx, gy = y0 - 1 + hy, gz = z0 - 1 + hz;
        uint4 vh = make_uint4(0,0,0,0), vl = make_uint4(0,0,0,0);
        if((unsigned)gx < 32u && (unsigned)gy < 32u && (unsigned)gz < 32u){
            size_t gidx = ((((size_t)b*32 + gx)*32 + gy)*32 + gz)*64 + cg*8;
            vh = *(const uint4*)(Ah + gidx);
            vl = *(const uint4*)(Al + gidx);
        }
        *(uint4*)(sm + hv*144 + cg*16)         = vh;
        *(uint4*)(sm + SM_AL + hv*144 + cg*16) = vl;
    }

    // ---- per-lane fragment addressing ----
    uint32_t sb = smem_u32(sm);
    int lane = tid & 31, wrp = tid >> 5;
    int rr = lane & 15, kh = lane >> 4;
    int m = wrp*16 + rr;
    int vx = m >> 5, vy = (m >> 3) & 3, vz = m & 7;
    uint32_t a_lane_off = (uint32_t)(kh*16);
    int tl = lane >> 3, lr = lane & 7;
    uint32_t w_lane = (uint32_t)((((tl>>1)*8 + lr)*144) + (tl&1)*16);
    uint32_t whb = sb + SM_WH + w_lane;
    uint32_t wlb = sb + SM_WL + w_lane;

    float C[8][4];
    #pragma unroll
    for(int g = 0; g < 8; g++){ C[g][0]=0.f; C[g][1]=0.f; C[g][2]=0.f; C[g][3]=0.f; }

    for(int tap = 0; tap < 27; tap++){
        __syncthreads();
        // stream this tap's 64x64 weight slice (hi+lo) into smem, pitch 144B
        for(int i = tid; i < 512; i += 256){
            int co = i >> 3, cg = i & 7;
            *(uint4*)(sm + SM_WH + co*144 + cg*16) = *(const uint4*)(Wg + (size_t)tap*4096 + co*64 + cg*8);
            *(uint4*)(sm + SM_WL + co*144 + cg*16) = *(const uint4*)(Wg + (size_t)(27+tap)*4096 + co*64 + cg*8);
        }
        __syncthreads();

        int dx = tap/9, rem2 = tap - 9*dx;
        int dy = rem2/3, dz = rem2 - 3*dy;
        uint32_t aH = sb + (uint32_t)((((vx+dx)*6 + (vy+dy))*10 + (vz+dz))*144) + a_lane_off;
        uint32_t aL = aH + SM_AL;

        #pragma unroll
        for(int kc = 0; kc < 4; kc++){
            uint32_t ah[4], al[4];
            uint32_t bh[4][4], bl[4][4];
            ldmx4(ah[0], ah[1], ah[2], ah[3], aH + kc*32);
            ldmx4(al[0], al[1], al[2], al[3], aL + kc*32);
            #pragma unroll
            for(int j = 0; j < 4; j++)
                ldmx4(bh[j][0], bh[j][1], bh[j][2], bh[j][3], whb + j*2304 + kc*32);
            #pragma unroll
            for(int j = 0; j < 4; j++)
                ldmx4(bl[j][0], bl[j][1], bl[j][2], bl[j][3], wlb + j*2304 + kc*32);
            #pragma unroll
            for(int j = 0; j < 4; j++){
                mma16816(C[2*j],   ah, &bh[j][0]);
                mma16816(C[2*j+1], ah, &bh[j][2]);
            }
            #pragma unroll
            for(int j = 0; j < 4; j++){
                mma16816(C[2*j],   al, &bh[j][0]);
                mma16816(C[2*j+1], al, &bh[j][2]);
            }
            #pragma unroll
            for(int j = 0; j < 4; j++){
                mma16816(C[2*j],   ah, &bl[j][0]);
                mma16816(C[2*j+1], ah, &bl[j][2]);
            }
        }
    }

    // ---- epilogue: BN + leaky, store ----
    int tr = lane >> 2, col0 = (lane & 3)*2;
    #pragma unroll
    for(int half = 0; half < 2; half++){
        int mm = wrp*16 + tr + half*8;
        int xg = x0 + (mm >> 5), yg = y0 + ((mm >> 3) & 3), zg = z0 + (mm & 7);
        size_t vbase = ((((size_t)b*32 + xg)*32 + yg)*32 + zg)*64;
        #pragma unroll
        for(int g = 0; g < 8; g++){
            int co = g*8 + col0;
            float y0v = C[g][half*2+0]*s_scale[co]   + s_bias[co];
            float y1v = C[g][half*2+1]*s_scale[co+1] + s_bias[co+1];
            y0v = (y0v > 0.f) ? y0v : 0.1f*y0v;
            y1v = (y1v > 0.f) ? y1v : 0.1f*y1v;
            if(mode){
                float2 st; st.x = y0v; st.y = y1v;
                *(float2*)(g_vox2 + vbase + co) = st;
            } else {
                __nv_bfloat16 h0 = __float2bfloat16(y0v);
                __nv_bfloat16 h1 = __float2bfloat16(y1v);
                __nv_bfloat16 l0 = __float2bfloat16(y0v - __bfloat162float(h0));
                __nv_bfloat16 l1 = __float2bfloat16(y1v - __bfloat162float(h1));
                uint32_t ph = (uint32_t)__bfloat16_as_ushort(h0) | ((uint32_t)__bfloat16_as_ushort(h1) << 16);
                uint32_t pl = (uint32_t)__bfloat16_as_ushort(l0) | ((uint32_t)__bfloat16_as_ushort(l1) << 16);
                *(uint32_t*)((__nv_bfloat16*)g_v1h + vbase + co) = ph;
                *(uint32_t*)((__nv_bfloat16*)g_v1l + vbase + co) = pl;
            }
        }
    }
}

// ---------------- devoxelize (gather) + point-branch MLP ----------------
__global__ void __launch_bounds__(256) k_devox(const float* __restrict__ coords,
        const float* __restrict__ mlpw, const float* __restrict__ mlpb,
        const float* __restrict__ bg, const float* __restrict__ bb,
        const float* __restrict__ bm, const float* __restrict__ bv,
        float* __restrict__ outp){
    __shared__ float s_feat[32*65];
    __shared__ float s_mw[64*65];
    __shared__ int   s_ci[256];
    __shared__ float s_cw[256];
    int tid = threadIdx.x;
    int blk = blockIdx.x;
    int b = blk >> 10; int n0 = (blk & 1023)*32;

    const float* fsrc = g_featT + ((size_t)b*NPTS + n0)*64;
    for(int i = tid; i < 2048; i += 256) s_feat[(i>>6)*65 + (i&63)] = fsrc[i];
    for(int i = tid; i < 4096; i += 256){ int co = i>>6, ci = i&63; s_mw[ci*65 + co] = mlpw[i]; }
    {
        int pn = tid >> 3, corner = tid & 7;
        int n = n0 + pn;
        float sc = g_scale[b];
        float vx = fminf(fmaxf(((coords[((size_t)b*3+0)*NPTS+n] - g_mean[b*3+0])*sc + 0.5f)*32.f, 0.f), 31.f);
        float vy = fminf(fmaxf(((coords[((size_t)b*3+1)*NPTS+n] - g_mean[b*3+1])*sc + 0.5f)*32.f, 0.f), 31.f);
        float vz = fminf(fmaxf(((coords[((size_t)b*3+2)*NPTS+n] - g_mean[b*3+2])*sc + 0.5f)*32.f, 0.f), 31.f);
        int lx = (int)floorf(vx), ly = (int)floorf(vy), lz = (int)floorf(vz);
        float fx = vx - lx, fy = vy - ly, fz = vz - lz;
        int dxb = corner >> 2, dyb = (corner >> 1) & 1, dzb = corner & 1;
        int xi = min(lx+dxb,31), yi = min(ly+dyb,31), zi = min(lz+dzb,31);
        s_ci[tid] = (xi*32 + yi)*32 + zi;
        s_cw[tid] = (dxb ? fx : 1.f-fx) * (dyb ? fy : 1.f-fy) * (dzb ? fz : 1.f-fz);
    }
    __syncthreads();

    int pn = tid & 31, cg = tid >> 5;
    int n = n0 + pn;
    float acc[8];
    #pragma unroll
    for(int j = 0; j < 8; j++) acc[j] = 0.f;
    for(int ci = 0; ci < 64; ci++){
        float f = s_feat[pn*65 + ci];
        #pragma unroll
        for(int j = 0; j < 8; j++) acc[j] += s_mw[ci*65 + cg*8 + j] * f;
    }
    float res[8];
    #pragma unroll
    for(int j = 0; j < 8; j++){
        int co = cg*8 + j;
        float s  = bg[co] * rsqrtf(bv[co] + 1e-4f);
        float bc = (mlpb[co] - bm[co]) * s + bb[co];
        res[j] = fmaxf(acc[j]*s + bc, 0.f);
    }
    #pragma unroll
    for(int corner = 0; corner < 8; corner++){
        int vi = s_ci[pn*8 + corner];
        float w = s_cw[pn*8 + corner];
        const float4* src = (const float4*)(g_vox2 + ((size_t)b*R3 + vi)*64 + cg*8);
        float4 v0 = src[0], v1 = src[1];
        res[0] += w*v0.x; res[1] += w*v0.y; res[2] += w*v0.z; res[3] += w*v0.w;
        res[4] += w*v1.x; res[5] += w*v1.y; res[6] += w*v1.z; res[7] += w*v1.w;
    }
    #pragma unroll
    for(int j = 0; j < 8; j++)
        outp[((size_t)b*64 + cg*8 + j)*NPTS + n] = res[j];
}

// ---------------- copy coords ----------------
__global__ void k_copy(const float* __restrict__ coords, float* __restrict__ dst){
    int i = blockIdx.x*256 + threadIdx.x;
    if(i < BB*3*NPTS) dst[i] = coords[i];
}

// ---------------- launch ----------------
extern "C" void kernel_launch(void* const* d_in, const int* in_sizes, int n_in,
                              void* d_out, int out_size){
    const float* features = (const float*)d_in[0];
    const float* coords   = (const float*)d_in[1];
    const float* c1w = (const float*)d_in[2];
    const float* c1b = (const float*)d_in[3];
    const float* b1g = (const float*)d_in[4];
    const float* b1b = (const float*)d_in[5];
    const float* b1m = (const float*)d_in[6];
    const float* b1v = (const float*)d_in[7];
    const float* c2w = (const float*)d_in[8];
    const float* c2b = (const float*)d_in[9];
    const float* b2g = (const float*)d_in[10];
    const float* b2b = (const float*)d_in[11];
    const float* b2m = (const float*)d_in[12];
    const float* b2v = (const float*)d_in[13];
    const float* mw  = (const float*)d_in[14];
    const float* mb  = (const float*)d_in[15];
    const float* bpg = (const float*)d_in[16];
    const float* bpb = (const float*)d_in[17];
    const float* bpm = (const float*)d_in[18];
    const float* bpv = (const float*)d_in[19];
    float* out = (float*)d_out;

    cudaFuncSetAttribute(k_conv_mma, cudaFuncAttributeMaxDynamicSharedMemorySize, CONV_SMEM);

    k_zero   <<<1024, 256>>>();
    k_mean   <<<BB,   256>>>(coords);
    k_radius <<<BB,   256>>>(coords);
    k_tfeat  <<<dim3(NPTS/32, CIN/32, BB), dim3(32, 8)>>>(features);
    k_prepw  <<<(221184 + 255)/256, 256>>>(c1w, c2w);
    k_scatter<<<(BB*NPTS*64)/256, 256>>>(coords);
    k_hilo   <<<65536, 256>>>();
    k_conv_mma<<<2048, 256, CONV_SMEM>>>(0, c1b, b1g, b1b, b1m, b1v);
    k_conv_mma<<<2048, 256, CONV_SMEM>>>(1, c2b, b2g, b2b, b2m, b2v);
    k_devox  <<<BB*(NPTS/32), 256>>>(coords, mw, mb, bpg, bpb, bpm, bpv, out);
    k_copy   <<<(BB*3*NPTS + 255)/256, 256>>>(coords, out + (size_t)BB*COUT*NPTS);
}

// round 4
// speedup vs baseline: 2.3295x; 1.1987x over previous
#include <cuda_runtime.h>
#include <cuda_bf16.h>
#include <math.h>
#include <stdint.h>

#define BB    8
#define CIN   64
#define COUT  64
#define NPTS  32768
#define R3    32768

// ---------------- scratch (static __device__ — no allocations) ----------------
__device__ float g_featT[(size_t)BB*NPTS*CIN];            // [b][n][c]
__device__ float g_acc  [(size_t)BB*R3*CIN];              // [b][x][y][z][c]
__device__ float g_cnt  [BB*R3];
__device__ __nv_bfloat16 g_v0h[(size_t)BB*R3*CIN];        // voxelized hi  [b][x][y][z][c]
__device__ __nv_bfloat16 g_v0l[(size_t)BB*R3*CIN];        // voxelized lo
__device__ __nv_bfloat16 g_v1h[(size_t)BB*R3*COUT];       // conv1 out hi
__device__ __nv_bfloat16 g_v1l[(size_t)BB*R3*COUT];       // conv1 out lo
__device__ float g_vox2[(size_t)BB*R3*COUT];              // conv2 out fp32 [b][x][y][z][c]
__device__ __nv_bfloat16 g_wall[108*64*64];               // [which*54 + hl*27 + tap][co][ci]
__device__ float g_mean [BB*3];
__device__ float g_scale[BB];

// ---------------- helpers ----------------
__device__ __forceinline__ uint32_t smem_u32(const void* p){
    uint32_t a;
    asm("{ .reg .u64 t; cvta.to.shared.u64 t, %1; cvt.u32.u64 %0, t; }" : "=r"(a) : "l"(p));
    return a;
}
__device__ __forceinline__ void ldmx4(uint32_t &r0, uint32_t &r1, uint32_t &r2, uint32_t &r3, uint32_t a){
    asm volatile("ldmatrix.sync.aligned.m8n8.x4.shared.b16 {%0,%1,%2,%3}, [%4];"
        : "=r"(r0), "=r"(r1), "=r"(r2), "=r"(r3) : "r"(a));
}
__device__ __forceinline__ void mma16816(float* c, const uint32_t* a, const uint32_t* b){
    asm volatile("mma.sync.aligned.m16n8k16.row.col.f32.bf16.bf16.f32 "
        "{%0,%1,%2,%3}, {%4,%5,%6,%7}, {%8,%9}, {%0,%1,%2,%3};"
        : "+f"(c[0]), "+f"(c[1]), "+f"(c[2]), "+f"(c[3])
        : "r"(a[0]), "r"(a[1]), "r"(a[2]), "r"(a[3]), "r"(b[0]), "r"(b[1]));
}
__device__ __forceinline__ void red_v4(float* gptr, float x, float y, float z, float w){
    asm volatile("red.global.add.v4.f32 [%0], {%1,%2,%3,%4};"
        :: "l"(__cvta_generic_to_global(gptr)), "f"(x), "f"(y), "f"(z), "f"(w) : "memory");
}
__device__ __forceinline__ void red_s(float* gptr, float x){
    asm volatile("red.global.add.f32 [%0], %1;"
        :: "l"(__cvta_generic_to_global(gptr)), "f"(x) : "memory");
}
__device__ __forceinline__ void cp_async16(uint32_t dst, const void* src){
    asm volatile("cp.async.ca.shared.global [%0], [%1], 16;"
        :: "r"(dst), "l"(__cvta_generic_to_global(src)) : "memory");
}

// ---------------- zero scratch ----------------
__global__ void k_zero(){
    size_t stride = (size_t)gridDim.x * blockDim.x;
    size_t t0 = (size_t)blockIdx.x * blockDim.x + threadIdx.x;
    for(size_t i = t0; i < (size_t)BB*R3*CIN; i += stride) g_acc[i] = 0.f;
    for(size_t i = t0; i < (size_t)BB*R3; i += stride) g_cnt[i] = 0.f;
}

// ---------------- per-batch mean ----------------
__global__ void k_mean(const float* __restrict__ coords){
    __shared__ float sh[256];
    int b = blockIdx.x, tid = threadIdx.x;
    for(int a = 0; a < 3; a++){
        float s = 0.f;
        for(int n = tid; n < NPTS; n += 256) s += coords[((size_t)b*3 + a)*NPTS + n];
        sh[tid] = s; __syncthreads();
        for(int off = 128; off; off >>= 1){ if(tid < off) sh[tid] += sh[tid+off]; __syncthreads(); }
        if(tid == 0) g_mean[b*3 + a] = sh[0] / (float)NPTS;
        __syncthreads();
    }
}

// ---------------- per-batch max radius -> scale ----------------
__global__ void k_radius(const float* __restrict__ coords){
    __shared__ float sh[256];
    int b = blockIdx.x, tid = threadIdx.x;
    float m0 = g_mean[b*3+0], m1 = g_mean[b*3+1], m2 = g_mean[b*3+2];
    float mx = 0.f;
    for(int n = tid; n < NPTS; n += 256){
        float dx = coords[((size_t)b*3+0)*NPTS + n] - m0;
        float dy = coords[((size_t)b*3+1)*NPTS + n] - m1;
        float dz = coords[((size_t)b*3+2)*NPTS + n] - m2;
        mx = fmaxf(mx, dx*dx + dy*dy + dz*dz);
    }
    sh[tid] = mx; __syncthreads();
    for(int off = 128; off; off >>= 1){ if(tid < off) sh[tid] = fmaxf(sh[tid], sh[tid+off]); __syncthreads(); }
    if(tid == 0) g_scale[b] = 1.0f / (2.0f * sqrtf(sh[0]) * (1.0f + 1e-6f));
}

// ---------------- transpose features [b][c][n] -> [b][n][c] ----------------
__global__ void k_tfeat(const float* __restrict__ f){
    __shared__ float s[32][33];
    int b = blockIdx.z;
    int n = blockIdx.x*32 + threadIdx.x;
    int cbase = blockIdx.y*32;
    #pragma unroll
    for(int j = 0; j < 4; j++){
        int c = cbase + threadIdx.y + j*8;
        s[threadIdx.y + j*8][threadIdx.x] = f[((size_t)b*CIN + c)*NPTS + n];
    }
    __syncthreads();
    int c2 = cbase + threadIdx.x;
    #pragma unroll
    for(int j = 0; j < 4; j++){
        int n2 = blockIdx.x*32 + threadIdx.y + j*8;
        g_featT[((size_t)b*NPTS + n2)*CIN + c2] = s[threadIdx.x][threadIdx.y + j*8];
    }
}

// ---------------- weight prep: w[co][ci][tap] -> bf16 hi/lo [plane][co][ci] ----------------
__global__ void k_prepw(const float* __restrict__ w1, const float* __restrict__ w2){
    int idx = blockIdx.x*256 + threadIdx.x;   // 2*27*4096 = 221184
    if(idx >= 221184) return;
    int which = idx / 110592;
    int r = idx - which*110592;
    int tap = r >> 12;
    int co  = (r >> 6) & 63;
    int ci  = r & 63;
    const float* src = which ? w2 : w1;
    float v = src[(co*64 + ci)*27 + tap];
    __nv_bfloat16 h = __float2bfloat16(v);
    float lo = v - __bfloat162float(h);
    g_wall[(which*54 + tap)*4096 + co*64 + ci]      = h;
    g_wall[(which*54 + 27 + tap)*4096 + co*64 + ci] = __float2bfloat16(lo);
}

// ---------------- trilinear scatter (vector reductions) ----------------
__global__ void k_scatter(const float* __restrict__ coords){
    int t = blockIdx.x*256 + threadIdx.x;     // BB*NPTS*16 threads
    int c4 = t & 15;
    int p = t >> 4;
    int b = p >> 15;
    int n = p & (NPTS-1);
    float sc = g_scale[b];
    float vx = fminf(fmaxf(((coords[((size_t)b*3+0)*NPTS+n] - g_mean[b*3+0])*sc + 0.5f)*32.f, 0.f), 31.f);
    float vy = fminf(fmaxf(((coords[((size_t)b*3+1)*NPTS+n] - g_mean[b*3+1])*sc + 0.5f)*32.f, 0.f), 31.f);
    float vz = fminf(fmaxf(((coords[((size_t)b*3+2)*NPTS+n] - g_mean[b*3+2])*sc + 0.5f)*32.f, 0.f), 31.f);
    int lx = (int)floorf(vx), ly = (int)floorf(vy), lz = (int)floorf(vz);
    float fx = vx - lx, fy = vy - ly, fz = vz - lz;
    float4 f = *(const float4*)(g_featT + (size_t)p*64 + c4*4);
    #pragma unroll
    for(int corner = 0; corner < 8; corner++){
        int dxb = corner >> 2, dyb = (corner >> 1) & 1, dzb = corner & 1;
        int xi = min(lx + dxb, 31), yi = min(ly + dyb, 31), zi = min(lz + dzb, 31);
        float w = (dxb ? fx : 1.f-fx) * (dyb ? fy : 1.f-fy) * (dzb ? fz : 1.f-fz);
        int vi = (xi*32 + yi)*32 + zi;
        float* base = g_acc + ((size_t)b*R3 + vi)*64 + c4*4;
        red_v4(base, w*f.x, w*f.y, w*f.z, w*f.w);
        if(c4 == 0) red_s(&g_cnt[b*R3 + vi], w);
    }
}

// ---------------- normalize + hi/lo bf16 split ----------------
__global__ void k_hilo(){
    size_t i = (size_t)blockIdx.x*256 + threadIdx.x;   // 16.7M
    float cw = g_cnt[i >> 6];
    float v = g_acc[i] / fmaxf(cw, 1e-8f);
    __nv_bfloat16 h = __float2bfloat16(v);
    g_v0h[i] = h;
    g_v0l[i] = __float2bfloat16(v - __bfloat162float(h));
}

// ---------------- HMMA conv: 3x3x3, 64->64, bf16 hi/lo 3-pass, BN + leaky ----------------
// smem: A_hi @0 (51840), A_lo @51840 (51840), W buf0 @103680 (18432), W buf1 @122112 (18432)
#define SM_AL 51840
#define SM_W0 103680
#define SM_W1 122112
#define CONV_SMEM 140544

__global__ void __launch_bounds__(256, 1) k_conv_mma(int mode,
        const float* __restrict__ cb, const float* __restrict__ bg,
        const float* __restrict__ bb, const float* __restrict__ bm,
        const float* __restrict__ bv){
    extern __shared__ char sm[];
    __shared__ float s_scale[64], s_bias[64];

    const __nv_bfloat16* __restrict__ Ah = mode ? g_v1h : g_v0h;
    const __nv_bfloat16* __restrict__ Al = mode ? g_v1l : g_v0l;
    const __nv_bfloat16* __restrict__ Wg = g_wall + (size_t)mode*54*4096;

    int tid = threadIdx.x;
    int cta = blockIdx.x;
    int b  = cta >> 8;
    int x0 = ((cta >> 5) & 7) * 4;
    int y0 = ((cta >> 2) & 7) * 4;
    int z0 = (cta & 3) * 8;
    uint32_t sb = smem_u32(sm);

    // prefetch W(0) into buf0
    {
        #pragma unroll
        for(int k = 0; k < 4; k++){
            int ch = k*256 + tid;
            int hl = ch >> 9, r = ch & 511, co = r >> 3, cg = r & 7;
            cp_async16(sb + SM_W0 + hl*9216 + co*144 + cg*16,
                       Wg + (size_t)(hl*27 + 0)*4096 + co*64 + cg*8);
        }
        asm volatile("cp.async.commit_group;" ::: "memory");
    }

    if(tid < 64){
        float s = bg[tid] * rsqrtf(bv[tid] + 1e-4f);
        s_scale[tid] = s;
        s_bias[tid]  = (cb[tid] - bm[tid]) * s + bb[tid];
    }

    // ---- load halo 6x6x10 x 64ci (hi+lo), row pitch 144B ----
    for(int i = tid; i < 2880; i += 256){
        int hv = i >> 3, cg = i & 7;
        int hx = hv/60; int rem = hv - hx*60; int hy = rem/10; int hz = rem - hy*10;
        int gx = x0 - 1 + hx, gy = y0 - 1 + hy, gz = z0 - 1 + hz;
        uint4 vh = make_uint4(0,0,0,0), vl = make_uint4(0,0,0,0);
        if((unsigned)gx < 32u && (unsigned)gy < 32u && (unsigned)gz < 32u){
            size_t gidx = ((((size_t)b*32 + gx)*32 + gy)*32 + gz)*64 + cg*8;
            vh = *(const uint4*)(Ah + gidx);
            vl = *(const uint4*)(Al + gidx);
        }
        *(uint4*)(sm + hv*144 + cg*16)         = vh;
        *(uint4*)(sm + SM_AL + hv*144 + cg*16) = vl;
    }

    // ---- per-lane fragment addressing ----
    int lane = tid & 31, wrp = tid >> 5;
    int rr = lane & 15, kh = lane >> 4;
    int m = wrp*16 + rr;
    int vx = m >> 5, vy = (m >> 3) & 3, vz = m & 7;
    uint32_t a_lane_off = (uint32_t)(kh*16);
    int tl = lane >> 3, lr = lane & 7;
    uint32_t w_lane = (uint32_t)((((tl>>1)*8 + lr)*144) + (tl&1)*16);

    float C[8][4];
    #pragma unroll
    for(int g = 0; g < 8; g++){ C[g][0]=0.f; C[g][1]=0.f; C[g][2]=0.f; C[g][3]=0.f; }

    for(int tap = 0; tap < 27; tap++){
        if(tap < 26){
            uint32_t nb = ((tap+1) & 1) ? SM_W1 : SM_W0;
            #pragma unroll
            for(int k = 0; k < 4; k++){
                int ch = k*256 + tid;
                int hl = ch >> 9, r = ch & 511, co = r >> 3, cg = r & 7;
                cp_async16(sb + nb + hl*9216 + co*144 + cg*16,
                           Wg + (size_t)(hl*27 + tap+1)*4096 + co*64 + cg*8);
            }
            asm volatile("cp.async.commit_group;" ::: "memory");
            asm volatile("cp.async.wait_group 1;" ::: "memory");
        } else {
            asm volatile("cp.async.wait_group 0;" ::: "memory");
        }
        __syncthreads();

        uint32_t wb = (tap & 1) ? SM_W1 : SM_W0;
        uint32_t whb = sb + wb + w_lane;
        uint32_t wlb = whb + 9216;

        int dx = tap/9, rem2 = tap - 9*dx;
        int dy = rem2/3, dz = rem2 - 3*dy;
        uint32_t aH = sb + (uint32_t)((((vx+dx)*6 + (vy+dy))*10 + (vz+dz))*144) + a_lane_off;
        uint32_t aL = aH + SM_AL;

        #pragma unroll
        for(int kc = 0; kc < 4; kc++){
            uint32_t ah[4], al[4];
            uint32_t bh[4][4], bl[4][4];
            ldmx4(ah[0], ah[1], ah[2], ah[3], aH + kc*32);
            ldmx4(al[0], al[1], al[2], al[3], aL + kc*32);
            #pragma unroll
            for(int j = 0; j < 4; j++)
                ldmx4(bh[j][0], bh[j][1], bh[j][2], bh[j][3], whb + j*2304 + kc*32);
            #pragma unroll
            for(int j = 0; j < 4; j++)
                ldmx4(bl[j][0], bl[j][1], bl[j][2], bl[j][3], wlb + j*2304 + kc*32);
            #pragma unroll
            for(int j = 0; j < 4; j++){
                mma16816(C[2*j],   ah, &bh[j][0]);
                mma16816(C[2*j+1], ah, &bh[j][2]);
            }
            #pragma unroll
            for(int j = 0; j < 4; j++){
                mma16816(C[2*j],   al, &bh[j][0]);
                mma16816(C[2*j+1], al, &bh[j][2]);
            }
            #pragma unroll
            for(int j = 0; j < 4; j++){
                mma16816(C[2*j],   ah, &bl[j][0]);
                mma16816(C[2*j+1], ah, &bl[j][2]);
            }
        }
        __syncthreads();
    }

    // ---- epilogue: BN + leaky, store ----
    int tr = lane >> 2, col0 = (lane & 3)*2;
    #pragma unroll
    for(int half = 0; half < 2; half++){
        int mm = wrp*16 + tr + half*8;
        int xg = x0 + (mm >> 5), yg = y0 + ((mm >> 3) & 3), zg = z0 + (mm & 7);
        size_t vbase = ((((size_t)b*32 + xg)*32 + yg)*32 + zg)*64;
        #pragma unroll
        for(int g = 0; g < 8; g++){
            int co = g*8 + col0;
            float y0v = C[g][half*2+0]*s_scale[co]   + s_bias[co];
            float y1v = C[g][half*2+1]*s_scale[co+1] + s_bias[co+1];
            y0v = (y0v > 0.f) ? y0v : 0.1f*y0v;
            y1v = (y1v > 0.f) ? y1v : 0.1f*y1v;
            if(mode){
                float2 st; st.x = y0v; st.y = y1v;
                *(float2*)(g_vox2 + vbase + co) = st;
            } else {
                __nv_bfloat16 h0 = __float2bfloat16(y0v);
                __nv_bfloat16 h1 = __float2bfloat16(y1v);
                __nv_bfloat16 l0 = __float2bfloat16(y0v - __bfloat162float(h0));
                __nv_bfloat16 l1 = __float2bfloat16(y1v - __bfloat162float(h1));
                uint32_t ph = (uint32_t)__bfloat16_as_ushort(h0) | ((uint32_t)__bfloat16_as_ushort(h1) << 16);
                uint32_t pl = (uint32_t)__bfloat16_as_ushort(l0) | ((uint32_t)__bfloat16_as_ushort(l1) << 16);
                *(uint32_t*)((__nv_bfloat16*)g_v1h + vbase + co) = ph;
                *(uint32_t*)((__nv_bfloat16*)g_v1l + vbase + co) = pl;
            }
        }
    }
}

// ---------------- devoxelize (coalesced gather) + point-branch MLP ----------------
// dyn smem: s_mw @0 (16384B), s_out @16384 (4 warps * 2112 floats = 33792B),
//           s_f @50176 (4*256 floats = 4096B), s_scale @54272 (256B), s_bias @54528 (256B)
#define DEVOX_SMEM 54784

__global__ void __launch_bounds__(128) k_devox(const float* __restrict__ coords,
        const float* __restrict__ mlpw, const float* __restrict__ mlpb,
        const float* __restrict__ bg, const float* __restrict__ bb,
        const float* __restrict__ bm, const float* __restrict__ bv,
        float* __restrict__ outp){
    extern __shared__ char dsm[];
    float* s_mw    = (float*)dsm;                 // [ci][co] 64x64
    float* s_out   = (float*)(dsm + 16384);       // per warp 64*33
    float* s_f     = (float*)(dsm + 50176);       // per warp 4*64
    float* s_scale = (float*)(dsm + 54272);
    float* s_bias  = (float*)(dsm + 54528);

    int tid = threadIdx.x, lane = tid & 31, w = tid >> 5;
    int b = blockIdx.x >> 8;
    int n_base = (blockIdx.x & 255) * 128;

    for(int i = tid; i < 4096; i += 128){ int co = i >> 6, ci = i & 63; s_mw[ci*64 + co] = mlpw[i]; }
    if(tid < 64){
        float s = bg[tid] * rsqrtf(bv[tid] + 1e-4f);
        s_scale[tid] = s;
        s_bias[tid]  = (mlpb[tid] - bm[tid]) * s + bb[tid];
    }
    __syncthreads();

    float* my_out = s_out + w*2112;
    float* my_f   = s_f + w*256;
    int n0 = n_base + w*32;
    float s0 = s_scale[2*lane], s1 = s_scale[2*lane+1];
    float bi0 = s_bias[2*lane], bi1 = s_bias[2*lane+1];
    float scb = g_scale[b];
    float m0c = g_mean[b*3+0], m1c = g_mean[b*3+1], m2c = g_mean[b*3+2];

    for(int pg = 0; pg < 8; pg++){
        int n = n0 + pg*4;
        #pragma unroll
        for(int q = 0; q < 4; q++){
            float2 f2 = *(const float2*)(g_featT + ((size_t)b*NPTS + n + q)*64 + 2*lane);
            *(float2*)(my_f + q*64 + 2*lane) = f2;
        }
        __syncwarp();
        float a[4][2];
        #pragma unroll
        for(int q = 0; q < 4; q++){ a[q][0] = 0.f; a[q][1] = 0.f; }
        #pragma unroll 8
        for(int ci = 0; ci < 64; ci++){
            float2 wv = *(const float2*)(s_mw + ci*64 + 2*lane);
            #pragma unroll
            for(int q = 0; q < 4; q++){
                float f = my_f[q*64 + ci];
                a[q][0] += f*wv.x; a[q][1] += f*wv.y;
            }
        }
        #pragma unroll
        for(int q = 0; q < 4; q++){
            int n_ = n + q;
            float r0 = fmaxf(a[q][0]*s0 + bi0, 0.f);
            float r1 = fmaxf(a[q][1]*s1 + bi1, 0.f);
            float vx = fminf(fmaxf(((coords[((size_t)b*3+0)*NPTS+n_] - m0c)*scb + 0.5f)*32.f, 0.f), 31.f);
            float vy = fminf(fmaxf(((coords[((size_t)b*3+1)*NPTS+n_] - m1c)*scb + 0.5f)*32.f, 0.f), 31.f);
            float vz = fminf(fmaxf(((coords[((size_t)b*3+2)*NPTS+n_] - m2c)*scb + 0.5f)*32.f, 0.f), 31.f);
            int lx = (int)floorf(vx), ly = (int)floorf(vy), lz = (int)floorf(vz);
            float fx = vx - lx, fy = vy - ly, fz = vz - lz;
            #pragma unroll
            for(int corner = 0; corner < 8; corner++){
                int dxb = corner >> 2, dyb = (corner >> 1) & 1, dzb = corner & 1;
                int xi = min(lx+dxb,31), yi = min(ly+dyb,31), zi = min(lz+dzb,31);
                float wgt = (dxb ? fx : 1.f-fx) * (dyb ? fy : 1.f-fy) * (dzb ? fz : 1.f-fz);
                int vi = (xi*32 + yi)*32 + zi;
                float2 v = *(const float2*)(g_vox2 + ((size_t)b*R3 + vi)*64 + 2*lane);
                r0 += wgt*v.x; r1 += wgt*v.y;
            }
            my_out[(2*lane)*33   + pg*4 + q] = r0;
            my_out[(2*lane+1)*33 + pg*4 + q] = r1;
        }
    }
    __syncwarp();
    for(int r = 0; r < 64; r++)
        outp[((size_t)b*64 + r)*NPTS + n0 + lane] = my_out[r*33 + lane];
}

// ---------------- copy coords ----------------
__global__ void k_copy(const float* __restrict__ coords, float* __restrict__ dst){
    int i = blockIdx.x*256 + threadIdx.x;
    if(i < BB*3*NPTS) dst[i] = coords[i];
}

// ---------------- launch ----------------
extern "C" void kernel_launch(void* const* d_in, const int* in_sizes, int n_in,
                              void* d_out, int out_size){
    const float* features = (const float*)d_in[0];
    const float* coords   = (const float*)d_in[1];
    const float* c1w = (const float*)d_in[2];
    const float* c1b = (const float*)d_in[3];
    const float* b1g = (const float*)d_in[4];
    const float* b1b = (const float*)d_in[5];
    const float* b1m = (const float*)d_in[6];
    const float* b1v = (const float*)d_in[7];
    const float* c2w = (const float*)d_in[8];
    const float* c2b = (const float*)d_in[9];
    const float* b2g = (const float*)d_in[10];
    const float* b2b = (const float*)d_in[11];
    const float* b2m = (const float*)d_in[12];
    const float* b2v = (const float*)d_in[13];
    const float* mw  = (const float*)d_in[14];
    const float* mb  = (const float*)d_in[15];
    const float* bpg = (const float*)d_in[16];
    const float* bpb = (const float*)d_in[17];
    const float* bpm = (const float*)d_in[18];
    const float* bpv = (const float*)d_in[19];
    float* out = (float*)d_out;

    cudaFuncSetAttribute(k_conv_mma, cudaFuncAttributeMaxDynamicSharedMemorySize, CONV_SMEM);
    cudaFuncSetAttribute(k_devox, cudaFuncAttributeMaxDynamicSharedMemorySize, DEVOX_SMEM);

    k_zero   <<<2048, 256>>>();
    k_mean   <<<BB,   256>>>(coords);
    k_radius <<<BB,   256>>>(coords);
    k_tfeat  <<<dim3(NPTS/32, CIN/32, BB), dim3(32, 8)>>>(features);
    k_prepw  <<<(221184 + 255)/256, 256>>>(c1w, c2w);
    k_scatter<<<(BB*NPTS*16)/256, 256>>>(coords);
    k_hilo   <<<65536, 256>>>();
    k_conv_mma<<<2048, 256, CONV_SMEM>>>(0, c1b, b1g, b1b, b1m, b1v);
    k_conv_mma<<<2048, 256, CONV_SMEM>>>(1, c2b, b2g, b2b, b2m, b2v);
    k_devox  <<<2048, 128, DEVOX_SMEM>>>(coords, mw, mb, bpg, bpb, bpm, bpv, out);
    k_copy   <<<(BB*3*NPTS + 255)/256, 256>>>(coords, out + (size_t)BB*COUT*NPTS);
}

// round 6
// speedup vs baseline: 3.3182x; 1.4244x over previous
#include <cuda_runtime.h>
#include <cuda_fp16.h>
#include <math.h>
#include <stdint.h>

#define BB    8
#define CIN   64
#define COUT  64
#define NPTS  32768
#define R3    32768

// ---------------- scratch (static __device__ — no allocations) ----------------
__device__ float g_featT[(size_t)BB*NPTS*CIN];            // [b][n][c]
__device__ float g_acc  [(size_t)BB*R3*CIN];              // [b][x][y][z][c]
__device__ float g_cnt  [BB*R3];
__device__ __half g_v0h[(size_t)BB*R3*CIN];               // voxelized hi  [b][x][y][z][c]
__device__ __half g_v0l[(size_t)BB*R3*CIN];               // voxelized lo
__device__ __half g_v1h[(size_t)BB*R3*COUT];              // conv1 out hi
__device__ __half g_v1l[(size_t)BB*R3*COUT];              // conv1 out lo
__device__ float g_vox2[(size_t)BB*R3*COUT];              // conv2 out fp32 [b][x][y][z][c]
__device__ __half g_wh [2*27*64*64];                      // [which*27 + tap][co][ci]  fp16
__device__ float g_mean [BB*3];
__device__ float g_scale[BB];

// ---------------- helpers ----------------
__device__ __forceinline__ uint32_t smem_u32(const void* p){
    uint32_t a;
    asm("{ .reg .u64 t; cvta.to.shared.u64 t, %1; cvt.u32.u64 %0, t; }" : "=r"(a) : "l"(p));
    return a;
}
__device__ __forceinline__ void ldmx4(uint32_t &r0, uint32_t &r1, uint32_t &r2, uint32_t &r3, uint32_t a){
    asm volatile("ldmatrix.sync.aligned.m8n8.x4.shared.b16 {%0,%1,%2,%3}, [%4];"
        : "=r"(r0), "=r"(r1), "=r"(r2), "=r"(r3) : "r"(a));
}
__device__ __forceinline__ void mma16816(float* c, const uint32_t* a, const uint32_t* b){
    asm volatile("mma.sync.aligned.m16n8k16.row.col.f32.f16.f16.f32 "
        "{%0,%1,%2,%3}, {%4,%5,%6,%7}, {%8,%9}, {%0,%1,%2,%3};"
        : "+f"(c[0]), "+f"(c[1]), "+f"(c[2]), "+f"(c[3])
        : "r"(a[0]), "r"(a[1]), "r"(a[2]), "r"(a[3]), "r"(b[0]), "r"(b[1]));
}
__device__ __forceinline__ void red_v4(float* gptr, float x, float y, float z, float w){
    asm volatile("red.global.add.v4.f32 [%0], {%1,%2,%3,%4};"
        :: "l"(__cvta_generic_to_global(gptr)), "f"(x), "f"(y), "f"(z), "f"(w) : "memory");
}
__device__ __forceinline__ void red_s(float* gptr, float x){
    asm volatile("red.global.add.f32 [%0], %1;"
        :: "l"(__cvta_generic_to_global(gptr)), "f"(x) : "memory");
}
__device__ __forceinline__ void cp_async16(uint32_t dst, const void* src){
    asm volatile("cp.async.ca.shared.global [%0], [%1], 16;"
        :: "r"(dst), "l"(__cvta_generic_to_global(src)) : "memory");
}

// ---------------- zero scratch ----------------
__global__ void k_zero(){
    size_t stride = (size_t)gridDim.x * blockDim.x;
    size_t t0 = (size_t)blockIdx.x * blockDim.x + threadIdx.x;
    for(size_t i = t0; i < (size_t)BB*R3*CIN; i += stride) g_acc[i] = 0.f;
    for(size_t i = t0; i < (size_t)BB*R3; i += stride) g_cnt[i] = 0.f;
}

// ---------------- per-batch mean ----------------
__global__ void k_mean(const float* __restrict__ coords){
    __shared__ float sh[256];
    int b = blockIdx.x, tid = threadIdx.x;
    for(int a = 0; a < 3; a++){
        float s = 0.f;
        for(int n = tid; n < NPTS; n += 256) s += coords[((size_t)b*3 + a)*NPTS + n];
        sh[tid] = s; __syncthreads();
        for(int off = 128; off; off >>= 1){ if(tid < off) sh[tid] += sh[tid+off]; __syncthreads(); }
        if(tid == 0) g_mean[b*3 + a] = sh[0] / (float)NPTS;
        __syncthreads();
    }
}

// ---------------- per-batch max radius -> scale ----------------
__global__ void k_radius(const float* __restrict__ coords){
    __shared__ float sh[256];
    int b = blockIdx.x, tid = threadIdx.x;
    float m0 = g_mean[b*3+0], m1 = g_mean[b*3+1], m2 = g_mean[b*3+2];
    float mx = 0.f;
    for(int n = tid; n < NPTS; n += 256){
        float dx = coords[((size_t)b*3+0)*NPTS + n] - m0;
        float dy = coords[((size_t)b*3+1)*NPTS + n] - m1;
        float dz = coords[((size_t)b*3+2)*NPTS + n] - m2;
        mx = fmaxf(mx, dx*dx + dy*dy + dz*dz);
    }
    sh[tid] = mx; __syncthreads();
    for(int off = 128; off; off >>= 1){ if(tid < off) sh[tid] = fmaxf(sh[tid], sh[tid+off]); __syncthreads(); }
    if(tid == 0) g_scale[b] = 1.0f / (2.0f * sqrtf(sh[0]) * (1.0f + 1e-6f));
}

// ---------------- transpose features [b][c][n] -> [b][n][c] ----------------
__global__ void k_tfeat(const float* __restrict__ f){
    __shared__ float s[32][33];
    int b = blockIdx.z;
    int n = blockIdx.x*32 + threadIdx.x;
    int cbase = blockIdx.y*32;
    #pragma unroll
    for(int j = 0; j < 4; j++){
        int c = cbase + threadIdx.y + j*8;
        s[threadIdx.y + j*8][threadIdx.x] = f[((size_t)b*CIN + c)*NPTS + n];
    }
    __syncthreads();
    int c2 = cbase + threadIdx.x;
    #pragma unroll
    for(int j = 0; j < 4; j++){
        int n2 = blockIdx.x*32 + threadIdx.y + j*8;
        g_featT[((size_t)b*NPTS + n2)*CIN + c2] = s[threadIdx.x][threadIdx.y + j*8];
    }
}

// ---------------- weight prep: w[co][ci][tap] -> fp16 [which*27+tap][co][ci] ----------------
__global__ void k_prepw(const float* __restrict__ w1, const float* __restrict__ w2){
    int idx = blockIdx.x*256 + threadIdx.x;   // 2*27*4096 = 221184
    if(idx >= 221184) return;
    int which = idx / 110592;
    int r = idx - which*110592;
    int tap = r >> 12;
    int co  = (r >> 6) & 63;
    int ci  = r & 63;
    const float* src = which ? w2 : w1;
    g_wh[(which*27 + tap)*4096 + co*64 + ci] = __float2half(src[(co*64 + ci)*27 + tap]);
}

// ---------------- trilinear scatter (vector reductions) ----------------
__global__ void k_scatter(const float* __restrict__ coords){
    int t = blockIdx.x*256 + threadIdx.x;     // BB*NPTS*16 threads
    int c4 = t & 15;
    int p = t >> 4;
    int b = p >> 15;
    int n = p & (NPTS-1);
    float sc = g_scale[b];
    float vx = fminf(fmaxf(((coords[((size_t)b*3+0)*NPTS+n] - g_mean[b*3+0])*sc + 0.5f)*32.f, 0.f), 31.f);
    float vy = fminf(fmaxf(((coords[((size_t)b*3+1)*NPTS+n] - g_mean[b*3+1])*sc + 0.5f)*32.f, 0.f), 31.f);
    float vz = fminf(fmaxf(((coords[((size_t)b*3+2)*NPTS+n] - g_mean[b*3+2])*sc + 0.5f)*32.f, 0.f), 31.f);
    int lx = (int)floorf(vx), ly = (int)floorf(vy), lz = (int)floorf(vz);
    float fx = vx - lx, fy = vy - ly, fz = vz - lz;
    float4 f = *(const float4*)(g_featT + (size_t)p*64 + c4*4);
    #pragma unroll
    for(int corner = 0; corner < 8; corner++){
        int dxb = corner >> 2, dyb = (corner >> 1) & 1, dzb = corner & 1;
        int xi = min(lx + dxb, 31), yi = min(ly + dyb, 31), zi = min(lz + dzb, 31);
        float w = (dxb ? fx : 1.f-fx) * (dyb ? fy : 1.f-fy) * (dzb ? fz : 1.f-fz);
        int vi = (xi*32 + yi)*32 + zi;
        float* base = g_acc + ((size_t)b*R3 + vi)*64 + c4*4;
        red_v4(base, w*f.x, w*f.y, w*f.z, w*f.w);
        if(c4 == 0) red_s(&g_cnt[b*R3 + vi], w);
    }
}

// ---------------- normalize + hi/lo fp16 split (vectorized x4) ----------------
__global__ void k_hilo(){
    size_t i4 = ((size_t)blockIdx.x*256 + threadIdx.x)*4;   // 16.7M elems
    float inv = 1.0f / fmaxf(g_cnt[i4 >> 6], 1e-8f);
    float4 v = *(const float4*)(g_acc + i4);
    v.x *= inv; v.y *= inv; v.z *= inv; v.w *= inv;
    __half h0 = __float2half(v.x), h1 = __float2half(v.y);
    __half h2 = __float2half(v.z), h3 = __float2half(v.w);
    __half l0 = __float2half(v.x - __half2float(h0));
    __half l1 = __float2half(v.y - __half2float(h1));
    __half l2 = __float2half(v.z - __half2float(h2));
    __half l3 = __float2half(v.w - __half2float(h3));
    uint2 ph, pl;
    ph.x = (uint32_t)__half_as_ushort(h0) | ((uint32_t)__half_as_ushort(h1) << 16);
    ph.y = (uint32_t)__half_as_ushort(h2) | ((uint32_t)__half_as_ushort(h3) << 16);
    pl.x = (uint32_t)__half_as_ushort(l0) | ((uint32_t)__half_as_ushort(l1) << 16);
    pl.y = (uint32_t)__half_as_ushort(l2) | ((uint32_t)__half_as_ushort(l3) << 16);
    *(uint2*)(g_v0h + i4) = ph;
    *(uint2*)(g_v0l + i4) = pl;
}

// ---------------- HMMA conv: 3x3x3, 64->64, fp16 2-pass, M=256 tile, BN + leaky ----------------
// smem: A_hi @0 (93312), A_lo @93312 (93312), W0 @186624 (9216), W1 @195840 (9216)
#define SM_AL 93312
#define SM_W0 186624
#define SM_W1 195840
#define CONV_SMEM 205056

__global__ void __launch_bounds__(256, 1) k_conv_mma(int mode,
        const float* __restrict__ cb, const float* __restrict__ bg,
        const float* __restrict__ bb, const float* __restrict__ bm,
        const float* __restrict__ bv){
    extern __shared__ char sm[];
    __shared__ float s_scale[64], s_bias[64];

    const __half* __restrict__ Ah = mode ? g_v1h : g_v0h;
    const __half* __restrict__ Al = mode ? g_v1l : g_v0l;
    const __half* __restrict__ Wg = g_wh + (size_t)mode*27*4096;

    int tid = threadIdx.x;
    int cta = blockIdx.x;                  // 1024 = 8b * 8x * 8y * 2z
    int b  = cta >> 7; int rem = cta & 127;
    int x0 = (rem >> 4)*4;
    int y0 = ((rem >> 1) & 7)*4;
    int z0 = (rem & 1)*16;
    uint32_t sb = smem_u32(sm);

    // prefetch W(0) into W0 (64 rows x 8 chunks of 16B)
    #pragma unroll
    for(int k = 0; k < 2; k++){
        int ch = k*256 + tid;
        int co = ch >> 3, cg = ch & 7;
        cp_async16(sb + SM_W0 + co*144 + cg*16, Wg + co*64 + cg*8);
    }
    asm volatile("cp.async.commit_group;" ::: "memory");

    if(tid < 64){
        float s = bg[tid] * rsqrtf(bv[tid] + 1e-4f);
        s_scale[tid] = s;
        s_bias[tid]  = (cb[tid] - bm[tid]) * s + bb[tid];
    }

    // ---- load halo 6x6x18 x 64ci (hi+lo), row pitch 144B ----
    for(int i = tid; i < 5184; i += 256){
        int hv = i >> 3, cg = i & 7;
        int hx = hv/108; int r = hv - hx*108; int hy = r/18; int hz = r - hy*18;
        int gx = x0 - 1 + hx, gy = y0 - 1 + hy, gz = z0 - 1 + hz;
        uint4 vh = make_uint4(0,0,0,0), vl = make_uint4(0,0,0,0);
        if((unsigned)gx < 32u && (unsigned)gy < 32u && (unsigned)gz < 32u){
            size_t gidx = ((((size_t)b*32 + gx)*32 + gy)*32 + gz)*64 + cg*8;
            vh = *(const uint4*)(Ah + gidx);
            vl = *(const uint4*)(Al + gidx);
        }
        *(uint4*)(sm + hv*144 + cg*16)         = vh;
        *(uint4*)(sm + SM_AL + hv*144 + cg*16) = vl;
    }

    // ---- per-lane fragment addressing ----
    int lane = tid & 31, wrp = tid >> 5;
    int rr = lane & 15, kh = lane >> 4;
    int vxw = wrp >> 1;                    // voxel x (tile-local, 0..3)
    int vy0 = (wrp*2) & 3, vy1 = (wrp*2 + 1) & 3;
    int tl = lane >> 3, lr = lane & 7;
    uint32_t w_lane = (uint32_t)((((tl>>1)*8 + lr)*144) + (tl&1)*16);

    float C[2][8][4];
    #pragma unroll
    for(int t = 0; t < 2; t++)
        #pragma unroll
        for(int g = 0; g < 8; g++){ C[t][g][0]=0.f; C[t][g][1]=0.f; C[t][g][2]=0.f; C[t][g][3]=0.f; }

    for(int tap = 0; tap < 27; tap++){
        asm volatile("cp.async.wait_group 0;" ::: "memory");
        __syncthreads();
        if(tap < 26){
            uint32_t nb = ((tap+1) & 1) ? SM_W1 : SM_W0;
            #pragma unroll
            for(int k = 0; k < 2; k++){
                int ch = k*256 + tid;
                int co = ch >> 3, cg = ch & 7;
                cp_async16(sb + nb + co*144 + cg*16,
                           Wg + (size_t)(tap+1)*4096 + co*64 + cg*8);
            }
            asm volatile("cp.async.commit_group;" ::: "memory");
        }

        uint32_t wb = (tap & 1) ? SM_W1 : SM_W0;
        uint32_t whb = sb + wb + w_lane;

        int dx = tap/9, rem2 = tap - 9*dx;
        int dy = rem2/3, dz = rem2 - 3*dy;
        uint32_t a0 = sb + (uint32_t)((((vxw+dx)*6 + (vy0+dy))*18 + (rr+dz))*144) + kh*16;
        uint32_t a1 = sb + (uint32_t)((((vxw+dx)*6 + (vy1+dy))*18 + (rr+dz))*144) + kh*16;

        #pragma unroll
        for(int kc = 0; kc < 4; kc++){
            uint32_t ah0[4], al0[4], ah1[4], al1[4];
            uint32_t bw[4][4];
            ldmx4(ah0[0], ah0[1], ah0[2], ah0[3], a0 + kc*32);
            ldmx4(ah1[0], ah1[1], ah1[2], ah1[3], a1 + kc*32);
            ldmx4(al0[0], al0[1], al0[2], al0[3], a0 + SM_AL + kc*32);
            ldmx4(al1[0], al1[1], al1[2], al1[3], a1 + SM_AL + kc*32);
            #pragma unroll
            for(int j = 0; j < 4; j++)
                ldmx4(bw[j][0], bw[j][1], bw[j][2], bw[j][3], whb + j*2304 + kc*32);
            #pragma unroll
            for(int j = 0; j < 4; j++){
                mma16816(C[0][2*j],   ah0, &bw[j][0]);
                mma16816(C[0][2*j+1], ah0, &bw[j][2]);
                mma16816(C[1][2*j],   ah1, &bw[j][0]);
                mma16816(C[1][2*j+1], ah1, &bw[j][2]);
            }
            #pragma unroll
            for(int j = 0; j < 4; j++){
                mma16816(C[0][2*j],   al0, &bw[j][0]);
                mma16816(C[0][2*j+1], al0, &bw[j][2]);
                mma16816(C[1][2*j],   al1, &bw[j][0]);
                mma16816(C[1][2*j+1], al1, &bw[j][2]);
            }
        }
    }

    // ---- epilogue: BN + leaky, store ----
    int tr = lane >> 2, c2 = (lane & 3)*2;
    #pragma unroll
    for(int t = 0; t < 2; t++){
        #pragma unroll
        for(int half = 0; half < 2; half++){
            int mm = wrp*32 + t*16 + half*8 + tr;
            int xg = x0 + (mm >> 6), yg = y0 + ((mm >> 4) & 3), zg = z0 + (mm & 15);
            size_t vbase = ((((size_t)b*32 + xg)*32 + yg)*32 + zg)*64;
            #pragma unroll
            for(int g = 0; g < 8; g++){
                int co = g*8 + c2;
                float y0v = C[t][g][half*2+0]*s_scale[co]   + s_bias[co];
                float y1v = C[t][g][half*2+1]*s_scale[co+1] + s_bias[co+1];
                y0v = (y0v > 0.f) ? y0v : 0.1f*y0v;
                y1v = (y1v > 0.f) ? y1v : 0.1f*y1v;
                if(mode){
                    float2 st; st.x = y0v; st.y = y1v;
                    *(float2*)(g_vox2 + vbase + co) = st;
                } else {
                    __half h0 = __float2half(y0v);
                    __half h1 = __float2half(y1v);
                    __half l0 = __float2half(y0v - __half2float(h0));
                    __half l1 = __float2half(y1v - __half2float(h1));
                    uint32_t ph = (uint32_t)__half_as_ushort(h0) | ((uint32_t)__half_as_ushort(h1) << 16);
                    uint32_t pl = (uint32_t)__half_as_ushort(l0) | ((uint32_t)__half_as_ushort(l1) << 16);
                    *(uint32_t*)((__half*)g_v1h + vbase + co) = ph;
                    *(uint32_t*)((__half*)g_v1l + vbase + co) = pl;
                }
            }
        }
    }
}

// ---------------- devoxelize (coalesced gather) + point-branch MLP ----------------
#define DEVOX_SMEM 54784

__global__ void __launch_bounds__(128) k_devox(const float* __restrict__ coords,
        const float* __restrict__ mlpw, const float* __restrict__ mlpb,
        const float* __restrict__ bg, const float* __restrict__ bb,
        const float* __restrict__ bm, const float* __restrict__ bv,
        float* __restrict__ outp){
    extern __shared__ char dsm[];
    float* s_mw    = (float*)dsm;                 // [ci][co] 64x64
    float* s_out   = (float*)(dsm + 16384);       // per warp 64*33
    float* s_f     = (float*)(dsm + 50176);       // per warp 4*64
    float* s_scale = (float*)(dsm + 54272);
    float* s_bias  = (float*)(dsm + 54528);

    int tid = threadIdx.x, lane = tid & 31, w = tid >> 5;
    int b = blockIdx.x >> 8;
    int n_base = (blockIdx.x & 255) * 128;

    for(int i = tid; i < 4096; i += 128){ int co = i >> 6, ci = i & 63; s_mw[ci*64 + co] = mlpw[i]; }
    if(tid < 64){
        float s = bg[tid] * rsqrtf(bv[tid] + 1e-4f);
        s_scale[tid] = s;
        s_bias[tid]  = (mlpb[tid] - bm[tid]) * s + bb[tid];
    }
    __syncthreads();

    float* my_out = s_out + w*2112;
    float* my_f   = s_f + w*256;
    int n0 = n_base + w*32;
    float s0 = s_scale[2*lane], s1 = s_scale[2*lane+1];
    float bi0 = s_bias[2*lane], bi1 = s_bias[2*lane+1];
    float scb = g_scale[b];
    float m0c = g_mean[b*3+0], m1c = g_mean[b*3+1], m2c = g_mean[b*3+2];

    for(int pg = 0; pg < 8; pg++){
        int n = n0 + pg*4;
        #pragma unroll
        for(int q = 0; q < 4; q++){
            float2 f2 = *(const float2*)(g_featT + ((size_t)b*NPTS + n + q)*64 + 2*lane);
            *(float2*)(my_f + q*64 + 2*lane) = f2;
        }
        __syncwarp();
        float a[4][2];
        #pragma unroll
        for(int q = 0; q < 4; q++){ a[q][0] = 0.f; a[q][1] = 0.f; }
        #pragma unroll 8
        for(int ci = 0; ci < 64; ci++){
            float2 wv = *(const float2*)(s_mw + ci*64 + 2*lane);
            #pragma unroll
            for(int q = 0; q < 4; q++){
                float f = my_f[q*64 + ci];
                a[q][0] += f*wv.x; a[q][1] += f*wv.y;
            }
        }
        #pragma unroll
        for(int q = 0; q < 4; q++){
            int n_ = n + q;
            float r0 = fmaxf(a[q][0]*s0 + bi0, 0.f);
            float r1 = fmaxf(a[q][1]*s1 + bi1, 0.f);
            float vx = fminf(fmaxf(((coords[((size_t)b*3+0)*NPTS+n_] - m0c)*scb + 0.5f)*32.f, 0.f), 31.f);
            float vy = fminf(fmaxf(((coords[((size_t)b*3+1)*NPTS+n_] - m1c)*scb + 0.5f)*32.f, 0.f), 31.f);
            float vz = fminf(fmaxf(((coords[((size_t)b*3+2)*NPTS+n_] - m2c)*scb + 0.5f)*32.f, 0.f), 31.f);
            int lx = (int)floorf(vx), ly = (int)floorf(vy), lz = (int)floorf(vz);
            float fx = vx - lx, fy = vy - ly, fz = vz - lz;
            #pragma unroll
            for(int corner = 0; corner < 8; corner++){
                int dxb = corner >> 2, dyb = (corner >> 1) & 1, dzb = corner & 1;
                int xi = min(lx+dxb,31), yi = min(ly+dyb,31), zi = min(lz+dzb,31);
                float wgt = (dxb ? fx : 1.f-fx) * (dyb ? fy : 1.f-fy) * (dzb ? fz : 1.f-fz);
                int vi = (xi*32 + yi)*32 + zi;
                float2 v = *(const float2*)(g_vox2 + ((size_t)b*R3 + vi)*64 + 2*lane);
                r0 += wgt*v.x; r1 += wgt*v.y;
            }
            my_out[(2*lane)*33   + pg*4 + q] = r0;
            my_out[(2*lane+1)*33 + pg*4 + q] = r1;
        }
    }
    __syncwarp();
    for(int r = 0; r < 64; r++)
        outp[((size_t)b*64 + r)*NPTS + n0 + lane] = my_out[r*33 + lane];
}

// ---------------- copy coords ----------------
__global__ void k_copy(const float* __restrict__ coords, float* __restrict__ dst){
    int i = blockIdx.x*256 + threadIdx.x;
    if(i < BB*3*NPTS) dst[i] = coords[i];
}

// ---------------- launch ----------------
extern "C" void kernel_launch(void* const* d_in, const int* in_sizes, int n_in,
                              void* d_out, int out_size){
    const float* features = (const float*)d_in[0];
    const float* coords   = (const float*)d_in[1];
    const float* c1w = (const float*)d_in[2];
    const float* c1b = (const float*)d_in[3];
    const float* b1g = (const float*)d_in[4];
    const float* b1b = (const float*)d_in[5];
    const float* b1m = (const float*)d_in[6];
    const float* b1v = (const float*)d_in[7];
    const float* c2w = (const float*)d_in[8];
    const float* c2b = (const float*)d_in[9];
    const float* b2g = (const float*)d_in[10];
    const float* b2b = (const float*)d_in[11];
    const float* b2m = (const float*)d_in[12];
    const float* b2v = (const float*)d_in[13];
    const float* mw  = (const float*)d_in[14];
    const float* mb  = (const float*)d_in[15];
    const float* bpg = (const float*)d_in[16];
    const float* bpb = (const float*)d_in[17];
    const float* bpm = (const float*)d_in[18];
    const float* bpv = (const float*)d_in[19];
    float* out = (float*)d_out;

    cudaFuncSetAttribute(k_conv_mma, cudaFuncAttributeMaxDynamicSharedMemorySize, CONV_SMEM);
    cudaFuncSetAttribute(k_devox, cudaFuncAttributeMaxDynamicSharedMemorySize, DEVOX_SMEM);

    k_zero   <<<2048, 256>>>();
    k_mean   <<<BB,   256>>>(coords);
    k_radius <<<BB,   256>>>(coords);
    k_tfeat  <<<dim3(NPTS/32, CIN/32, BB), dim3(32, 8)>>>(features);
    k_prepw  <<<(221184 + 255)/256, 256>>>(c1w, c2w);
    k_scatter<<<(BB*NPTS*16)/256, 256>>>(coords);
    k_hilo   <<<16384, 256>>>();
    k_conv_mma<<<1024, 256, CONV_SMEM>>>(0, c1b, b1g, b1b, b1m, b1v);
    k_conv_mma<<<1024, 256, CONV_SMEM>>>(1, c2b, b2g, b2b, b2m, b2v);
    k_devox  <<<2048, 128, DEVOX_SMEM>>>(coords, mw, mb, bpg, bpb, bpm, bpv, out);
    k_copy   <<<(BB*3*NPTS + 255)/256, 256>>>(coords, out + (size_t)BB*COUT*NPTS);
}